// round 9
// baseline (speedup 1.0000x reference)
#include <cuda_runtime.h>
#include <math.h>

#define Hh    768
#define NB    32
#define NS    1024
#define NF    128
#define NP    256
#define NROWS (NB * NF)          // 4096
#define NC    28
#define CAP   64                 // max tokens per (b,field); Binom(1024,1/129) tail ~0
#define FW    4                  // fields (=warps) per block

// output segment offsets (floats), reference return order
#define OFF_MSR   0              // (B,F,2)
#define OFF_AGG   8192           // (B,F,9)
#define OFF_MSRS  45056          // (B,F,2)
#define OFF_DIM   53248          // (B,F,2)
#define OFF_KEY   61440          // (B,F,2)
#define OFF_PAIR  69632          // (B,P,2)
#define OFF_TYPE  86016          // (B,F,7)

__device__ float g_wT[NC * Hh];         // class-major transposed weights
__device__ float g_bias[NC];
__device__ float g_u[NROWS * 4];        // pair partial dots

// ---------------------------------------------------------------------------
// k0w: transpose all head weights into g_wT (one element per thread).
// ---------------------------------------------------------------------------
__global__ __launch_bounds__(256) void k0w(
    const float* __restrict__ Wmsr,  const float* __restrict__ bmsr,
    const float* __restrict__ Wagg,  const float* __restrict__ bagg,
    const float* __restrict__ Wdim,  const float* __restrict__ bdim,
    const float* __restrict__ Wmsrs, const float* __restrict__ bmsrs,
    const float* __restrict__ Wkey,  const float* __restrict__ bkey,
    const float* __restrict__ Wpair, const float* __restrict__ Wtype,
    const float* __restrict__ btype)
{
    const int idx = blockIdx.x * 256 + threadIdx.x;
    if (idx < NC * Hh) {
        const int c = idx / Hh, h = idx - c * Hh;
        float w;
        if      (c < 2)  w = Wmsr [h * 2 + c];
        else if (c < 11) w = Wagg [h * 9 + (c - 2)];
        else if (c < 13) w = Wdim [h * 2 + (c - 11)];
        else if (c < 15) w = Wmsrs[h * 2 + (c - 13)];
        else if (c < 17) w = Wkey [h * 2 + (c - 15)];
        else if (c < 24) w = Wtype[h * 7 + (c - 17)];
        else if (c < 26) w = Wpair[h * 2 + (c - 24)];
        else             w = Wpair[(Hh + h) * 2 + (c - 26)];
        g_wT[c * Hh + h] = w;
    }
    if (idx < NC) {
        float bv = 0.f;
        if      (idx < 2)  bv = bmsr [idx];
        else if (idx < 11) bv = bagg [idx - 2];
        else if (idx < 13) bv = bdim [idx - 11];
        else if (idx < 15) bv = bmsrs[idx - 13];
        else if (idx < 17) bv = bkey [idx - 15];
        else if (idx < 24) bv = btype[idx - 17];
        g_bias[idx] = bv;               // pair classes: 0 (bias in K3)
    }
}

// ---------------------------------------------------------------------------
// k1_fused: block = 4 warps, one field per warp. Lane owns h = {j*128+lane*4}
// slices (6 float4). Warp-local scan, gather, logits, softmax, writes.
// ---------------------------------------------------------------------------
__device__ __forceinline__ void write_lsm(float* dst, const float* l, int n)
{
    float m = l[0];
    for (int i = 1; i < n; i++) m = fmaxf(m, l[i]);
    float s = 0.f;
    for (int i = 0; i < n; i++) s += expf(l[i] - m);
    const float lse = m + logf(s);
    for (int i = 0; i < n; i++) dst[i] = l[i] - lse;
}

__global__ __launch_bounds__(128) void k1_fused(
    const float* __restrict__ emb, const int* __restrict__ col,
    float* __restrict__ out)
{
    const int fgrp = blockIdx.x;             // 0..31
    const int b    = blockIdx.y;             // 0..31
    const int tid  = threadIdx.x;
    const int lane = tid & 31;
    const int w    = tid >> 5;               // warp = field-within-group

    __shared__ int sCol[NS];
    __shared__ int sList[FW][CAP];

    // stage col row (4 KB, coalesced)
    const int4* c4 = (const int4*)(col + b * NS);
    for (int i = tid; i < NS / 4; i += 128) ((int4*)sCol)[i] = c4[i];
    __syncthreads();

    // warp-private ballot scan for this warp's field
    const int field  = fgrp * FW + w;
    const int target = field + 1;            // segment 0 dropped
    int cnt = 0;
#pragma unroll 4
    for (int base = 0; base < NS; base += 32) {
        const int c = sCol[base + lane];
        const unsigned m = __ballot_sync(0xffffffffu, c == target);
        if (c == target) {
            const int pos = cnt + __popc(m & ((1u << lane) - 1u));
            if (pos < CAP) sList[w][pos] = base + lane;
        }
        cnt += __popc(m);                    // uniform across lanes
    }
    __syncwarp();
    const int n = min(cnt, CAP);

    // gather: mean over n rows; lane's slice = float4 at [j*32 + lane], j=0..5
    const float* rowbase = emb + (size_t)b * NS * Hh;
    float4 acc[6];
#pragma unroll
    for (int j = 0; j < 6; j++) acc[j] = make_float4(0.f, 0.f, 0.f, 0.f);

    int i = 0;
    for (; i + 2 <= n; i += 2) {             // 12 outstanding float4 / lane
        const float4* r0 = (const float4*)(rowbase + (size_t)sList[w][i]     * Hh);
        const float4* r1 = (const float4*)(rowbase + (size_t)sList[w][i + 1] * Hh);
        float4 x0[6], x1[6];
#pragma unroll
        for (int j = 0; j < 6; j++) x0[j] = r0[j * 32 + lane];
#pragma unroll
        for (int j = 0; j < 6; j++) x1[j] = r1[j * 32 + lane];
#pragma unroll
        for (int j = 0; j < 6; j++) {
            acc[j].x += x0[j].x + x1[j].x;
            acc[j].y += x0[j].y + x1[j].y;
            acc[j].z += x0[j].z + x1[j].z;
            acc[j].w += x0[j].w + x1[j].w;
        }
    }
    if (i < n) {
        const float4* r0 = (const float4*)(rowbase + (size_t)sList[w][i] * Hh);
#pragma unroll
        for (int j = 0; j < 6; j++) {
            float4 x = r0[j * 32 + lane];
            acc[j].x += x.x; acc[j].y += x.y; acc[j].z += x.z; acc[j].w += x.w;
        }
    }
    const float inv = 1.0f / (float)(n > 0 ? n : 1);
#pragma unroll
    for (int j = 0; j < 6; j++) {
        acc[j].x *= inv; acc[j].y *= inv; acc[j].z *= inv; acc[j].w *= inv;
    }

    // logits: 28 classes, warp-local dot + butterfly
    float l[NC];
#pragma unroll 4
    for (int c = 0; c < NC; c++) {
        const float4* wrow = (const float4*)(g_wT + (size_t)c * Hh);
        float s = 0.f;
#pragma unroll
        for (int j = 0; j < 6; j++) {
            const float4 q = wrow[j * 32 + lane];
            s += acc[j].x * q.x + acc[j].y * q.y + acc[j].z * q.z + acc[j].w * q.w;
        }
        s += __shfl_xor_sync(0xffffffffu, s, 16);
        s += __shfl_xor_sync(0xffffffffu, s, 8);
        s += __shfl_xor_sync(0xffffffffu, s, 4);
        s += __shfl_xor_sync(0xffffffffu, s, 2);
        s += __shfl_xor_sync(0xffffffffu, s, 1);
        l[c] = s + g_bias[c];
    }

    // lane 0: log_softmax per head + writes
    if (lane == 0) {
        const int row = b * NF + field;
        write_lsm(out + OFF_MSR  + row * 2, l + 0,  2);
        write_lsm(out + OFF_AGG  + row * 9, l + 2,  9);
        write_lsm(out + OFF_MSRS + row * 2, l + 13, 2);
        write_lsm(out + OFF_DIM  + row * 2, l + 11, 2);
        write_lsm(out + OFF_KEY  + row * 2, l + 15, 2);
        write_lsm(out + OFF_TYPE + row * 7, l + 17, 7);
        float* u = g_u + row * 4;            // pair partials (bias in k3)
        u[0] = l[24]; u[1] = l[25]; u[2] = l[26]; u[3] = l[27];
    }
}

// ---------------------------------------------------------------------------
// k3: pair head. One block per batch; stage the batch's g_u slab in smem.
// ---------------------------------------------------------------------------
__global__ __launch_bounds__(256) void k3_pair(
    const int* __restrict__ pidx, const float* __restrict__ bpair,
    float* __restrict__ out)
{
    __shared__ float sU[NF * 4];             // 2 KB
    __shared__ float sBp[2];
    const int b   = blockIdx.x;
    const int tid = threadIdx.x;

    const float4* u4 = (const float4*)(g_u + (size_t)b * NF * 4);
    for (int i = tid; i < NF; i += 256) ((float4*)sU)[i] = u4[i];
    if (tid < 2) sBp[tid] = bpair[tid];
    __syncthreads();

    const int2 pr = ((const int2*)pidx)[b * NP + tid];   // coalesced
    const float* u1 = sU + pr.x * 4;
    const float* u2 = sU + pr.y * 4;
    const float l0 = u1[0] + u2[2] + sBp[0];
    const float l1 = u1[1] + u2[3] + sBp[1];
    const float m  = fmaxf(l0, l1);
    const float lse = m + logf(expf(l0 - m) + expf(l1 - m));
    float2* o2 = (float2*)(out + OFF_PAIR);
    o2[b * NP + tid] = make_float2(l0 - lse, l1 - lse);
}

// ---------------------------------------------------------------------------
extern "C" void kernel_launch(void* const* d_in, const int* in_sizes, int n_in,
                              void* d_out, int out_size)
{
    const float* emb  = (const float*)d_in[0];
    const int*   col  = (const int*)d_in[1];
    const int*   pidx = (const int*)d_in[2];
    const int wb = n_in - 14;
    const float* Wmsr  = (const float*)d_in[wb + 0];
    const float* bmsr  = (const float*)d_in[wb + 1];
    const float* Wagg  = (const float*)d_in[wb + 2];
    const float* bagg  = (const float*)d_in[wb + 3];
    const float* Wdim  = (const float*)d_in[wb + 4];
    const float* bdim  = (const float*)d_in[wb + 5];
    const float* Wmsrs = (const float*)d_in[wb + 6];
    const float* bmsrs = (const float*)d_in[wb + 7];
    const float* Wkey  = (const float*)d_in[wb + 8];
    const float* bkey  = (const float*)d_in[wb + 9];
    const float* Wpair = (const float*)d_in[wb + 10];
    const float* bpair = (const float*)d_in[wb + 11];
    const float* Wtype = (const float*)d_in[wb + 12];
    const float* btype = (const float*)d_in[wb + 13];
    float* out = (float*)d_out;

    k0w<<<(NC * Hh + 255) / 256, 256>>>(Wmsr, bmsr, Wagg, bagg, Wdim, bdim,
                                        Wmsrs, bmsrs, Wkey, bkey,
                                        Wpair, Wtype, btype);

    k1_fused<<<dim3(NF / FW, NB), 128>>>(emb, col, out);

    k3_pair<<<NB, 256>>>(pidx, bpair, out);
}

// round 10
// speedup vs baseline: 1.2963x; 1.2963x over previous
#include <cuda_runtime.h>
#include <math.h>

#define Hh    768
#define NB    32
#define NS    1024
#define NF    128
#define NP    256
#define NROWS (NB * NF)          // 4096
#define NC    28
#define CAP   64                 // max tokens per (b,field); Binom(1024,1/129) tail ~0
#define FG    8                  // fields per block

// output segment offsets (floats), reference return order
#define OFF_MSR   0              // (B,F,2)
#define OFF_AGG   8192           // (B,F,9)
#define OFF_MSRS  45056          // (B,F,2)
#define OFF_DIM   53248          // (B,F,2)
#define OFF_KEY   61440          // (B,F,2)
#define OFF_PAIR  69632          // (B,P,2)
#define OFF_TYPE  86016          // (B,F,7)

__device__ float g_u[NROWS * 4];        // pair partial dots

// ---------------------------------------------------------------------------
#define BFLY5(s) do { \
    s += __shfl_xor_sync(0xffffffffu, s, 16); \
    s += __shfl_xor_sync(0xffffffffu, s, 8);  \
    s += __shfl_xor_sync(0xffffffffu, s, 4);  \
    s += __shfl_xor_sync(0xffffffffu, s, 2);  \
    s += __shfl_xor_sync(0xffffffffu, s, 1);  \
} while (0)

// Head with NCOLS classes, native layout [768][NCOLS]. Thread tid owns h rows
// 4tid..4tid+3 -> 4*NCOLS contiguous floats at Wbase + tid*4*NCOLS.
// Computes per-field partial dots, 5-level butterfly, lane0 -> sRed.
template<int NCOLS>
__device__ __forceinline__ void head_partial(
    const float* __restrict__ Wbase, int tid, int cbase,
    const float4 v[FG], int w, int lane, float* __restrict__ sRed)
{
    float qa[4 * NCOLS];
    const float4* P = (const float4*)Wbase + tid * NCOLS;
#pragma unroll
    for (int k = 0; k < NCOLS; k++) *(float4*)(qa + 4 * k) = P[k];
#pragma unroll
    for (int c = 0; c < NCOLS; c++) {
        float s[FG];
#pragma unroll
        for (int f = 0; f < FG; f++)
            s[f] = v[f].x * qa[c]
                 + v[f].y * qa[NCOLS + c]
                 + v[f].z * qa[2 * NCOLS + c]
                 + v[f].w * qa[3 * NCOLS + c];
#pragma unroll
        for (int f = 0; f < FG; f++) BFLY5(s[f]);
        if (lane == 0) {
#pragma unroll
            for (int f = 0; f < FG; f++)
                sRed[(w * NC + cbase + c) * FG + f] = s[f];
        }
    }
}

__device__ __forceinline__ void write_lsm(float* dst, const float* l, int n)
{
    float m = l[0];
    for (int i = 1; i < n; i++) m = fmaxf(m, l[i]);
    float s = 0.f;
    for (int i = 0; i < n; i++) s += expf(l[i] - m);
    const float lse = m + logf(s);
    for (int i = 0; i < n; i++) dst[i] = l[i] - lse;
}

// ---------------------------------------------------------------------------
// k1_fused: one block per (8 fields, batch). In-block ballot scan, paired
// gather, native-weight logits, fused log_softmax + writes + pair partials.
// ---------------------------------------------------------------------------
__global__ __launch_bounds__(192) void k1_fused(
    const float* __restrict__ emb, const int* __restrict__ col,
    const float* __restrict__ Wmsr,  const float* __restrict__ bmsr,
    const float* __restrict__ Wagg,  const float* __restrict__ bagg,
    const float* __restrict__ Wdim,  const float* __restrict__ bdim,
    const float* __restrict__ Wmsrs, const float* __restrict__ bmsrs,
    const float* __restrict__ Wkey,  const float* __restrict__ bkey,
    const float* __restrict__ Wpair, const float* __restrict__ Wtype,
    const float* __restrict__ btype,
    float* __restrict__ out)
{
    const int fg   = blockIdx.x;              // 0..15
    const int b    = blockIdx.y;              // 0..31
    const int tid  = threadIdx.x;             // 0..191
    const int lane = tid & 31;
    const int w    = tid >> 5;                // warp 0..5

    __shared__ int   sCol[NS];
    __shared__ int   sList[FG][CAP];
    __shared__ int   sCnt[FG];
    __shared__ float sRed[6 * NC * FG];
    __shared__ float sLog[FG][NC];
    __shared__ float sB[NC];

    // stage biases (native)
    if (tid < NC) {
        float bv = 0.f;
        if      (tid < 2)  bv = bmsr [tid];
        else if (tid < 11) bv = bagg [tid - 2];
        else if (tid < 13) bv = bdim [tid - 11];
        else if (tid < 15) bv = bmsrs[tid - 13];
        else if (tid < 17) bv = bkey [tid - 15];
        else if (tid < 24) bv = btype[tid - 17];
        sB[tid] = bv;                          // pair classes: 0 (bias in k3)
    }

    // stage col row (4 KB, coalesced)
    const int4* c4 = (const int4*)(col + b * NS);
    for (int i = tid; i < NS / 4; i += 192) ((int4*)sCol)[i] = c4[i];
    __syncthreads();

    // in-block list build: warp w covers fields {w, w+6}
    for (int f = w; f < FG; f += 6) {
        const int target = fg * FG + f + 1;   // segment 0 dropped
        int cnt = 0;
#pragma unroll 4
        for (int base = 0; base < NS; base += 32) {
            const int c = sCol[base + lane];
            const unsigned m = __ballot_sync(0xffffffffu, c == target);
            if (c == target) {
                const int pos = cnt + __popc(m & ((1u << lane) - 1u));
                if (pos < CAP) sList[f][pos] = base + lane;
            }
            cnt += __popc(m);
        }
        if (lane == 0) sCnt[f] = min(cnt, CAP);
    }
    __syncthreads();

    // paired gather: fields (2fp, 2fp+1) accumulate concurrently
    const float4* ebase = (const float4*)(emb + (size_t)b * NS * Hh) + tid;
    float4 v[FG];
#pragma unroll 1
    for (int fp = 0; fp < FG / 2; fp++) {
        const int f0 = 2 * fp, f1 = 2 * fp + 1;
        const int n0 = sCnt[f0], n1 = sCnt[f1];
        const int* l0 = sList[f0];
        const int* l1 = sList[f1];
        float4 A0 = make_float4(0.f,0.f,0.f,0.f), A1 = A0, B0 = A0, B1 = A0;
        const int m = min(n0, n1);
        int i = 0;
        for (; i + 2 <= m; i += 2) {          // 4 float4 in flight
            float4 xa = ebase[l0[i]     * (Hh/4)];
            float4 xb = ebase[l0[i + 1] * (Hh/4)];
            float4 ya = ebase[l1[i]     * (Hh/4)];
            float4 yb = ebase[l1[i + 1] * (Hh/4)];
            A0.x += xa.x; A0.y += xa.y; A0.z += xa.z; A0.w += xa.w;
            A1.x += xb.x; A1.y += xb.y; A1.z += xb.z; A1.w += xb.w;
            B0.x += ya.x; B0.y += ya.y; B0.z += ya.z; B0.w += ya.w;
            B1.x += yb.x; B1.y += yb.y; B1.z += yb.z; B1.w += yb.w;
        }
        int i0 = i;
        for (; i0 + 2 <= n0; i0 += 2) {
            float4 xa = ebase[l0[i0]     * (Hh/4)];
            float4 xb = ebase[l0[i0 + 1] * (Hh/4)];
            A0.x += xa.x; A0.y += xa.y; A0.z += xa.z; A0.w += xa.w;
            A1.x += xb.x; A1.y += xb.y; A1.z += xb.z; A1.w += xb.w;
        }
        if (i0 < n0) {
            float4 xa = ebase[l0[i0] * (Hh/4)];
            A0.x += xa.x; A0.y += xa.y; A0.z += xa.z; A0.w += xa.w;
        }
        int i1 = i;
        for (; i1 + 2 <= n1; i1 += 2) {
            float4 ya = ebase[l1[i1]     * (Hh/4)];
            float4 yb = ebase[l1[i1 + 1] * (Hh/4)];
            B0.x += ya.x; B0.y += ya.y; B0.z += ya.z; B0.w += ya.w;
            B1.x += yb.x; B1.y += yb.y; B1.z += yb.z; B1.w += yb.w;
        }
        if (i1 < n1) {
            float4 ya = ebase[l1[i1] * (Hh/4)];
            B0.x += ya.x; B0.y += ya.y; B0.z += ya.z; B0.w += ya.w;
        }
        const float inv0 = 1.0f / (float)(n0 > 0 ? n0 : 1);
        const float inv1 = 1.0f / (float)(n1 > 0 ? n1 : 1);
        v[f0].x = (A0.x + A1.x) * inv0; v[f0].y = (A0.y + A1.y) * inv0;
        v[f0].z = (A0.z + A1.z) * inv0; v[f0].w = (A0.w + A1.w) * inv0;
        v[f1].x = (B0.x + B1.x) * inv1; v[f1].y = (B0.y + B1.y) * inv1;
        v[f1].z = (B0.z + B1.z) * inv1; v[f1].w = (B0.w + B1.w) * inv1;
    }

    // logits: native weight loads (coalesced float4, L1-resident)
    head_partial<2>(Wmsr,         tid, 0,  v, w, lane, sRed);
    head_partial<9>(Wagg,         tid, 2,  v, w, lane, sRed);
    head_partial<2>(Wdim,         tid, 11, v, w, lane, sRed);
    head_partial<2>(Wmsrs,        tid, 13, v, w, lane, sRed);
    head_partial<2>(Wkey,         tid, 15, v, w, lane, sRed);
    head_partial<7>(Wtype,        tid, 17, v, w, lane, sRed);
    head_partial<2>(Wpair,        tid, 24, v, w, lane, sRed);   // top half
    head_partial<2>(Wpair + 1536, tid, 26, v, w, lane, sRed);   // bottom half
    __syncthreads();

    // cross-warp reduce: NC*FG = 224 cells, strided over 192 threads
    for (int idx = tid; idx < NC * FG; idx += 192) {
        const int c = idx >> 3, f = idx & 7;
        float s = sB[c];
#pragma unroll
        for (int ww = 0; ww < 6; ww++) s += sRed[(ww * NC + c) * FG + f];
        sLog[f][c] = s;
    }
    __syncthreads();

    if (tid < FG) {
        const int field = fg * FG + tid;
        const int row = b * NF + field;
        float l[NC];
#pragma unroll
        for (int c = 0; c < NC; c++) l[c] = sLog[tid][c];

        write_lsm(out + OFF_MSR  + row * 2, l + 0,  2);
        write_lsm(out + OFF_AGG  + row * 9, l + 2,  9);
        write_lsm(out + OFF_MSRS + row * 2, l + 13, 2);
        write_lsm(out + OFF_DIM  + row * 2, l + 11, 2);
        write_lsm(out + OFF_KEY  + row * 2, l + 15, 2);
        write_lsm(out + OFF_TYPE + row * 7, l + 17, 7);

        float* u = g_u + row * 4;
        u[0] = l[24]; u[1] = l[25]; u[2] = l[26]; u[3] = l[27];
    }
}

// ---------------------------------------------------------------------------
// k3: pair head. One block per batch; stage the batch's g_u slab in smem.
// ---------------------------------------------------------------------------
__global__ __launch_bounds__(256) void k3_pair(
    const int* __restrict__ pidx, const float* __restrict__ bpair,
    float* __restrict__ out)
{
    __shared__ float sU[NF * 4];             // 2 KB
    __shared__ float sBp[2];
    const int b   = blockIdx.x;
    const int tid = threadIdx.x;

    const float4* u4 = (const float4*)(g_u + (size_t)b * NF * 4);
    for (int i = tid; i < NF; i += 256) ((float4*)sU)[i] = u4[i];
    if (tid < 2) sBp[tid] = bpair[tid];
    __syncthreads();

    const int2 pr = ((const int2*)pidx)[b * NP + tid];   // coalesced
    const float* u1 = sU + pr.x * 4;
    const float* u2 = sU + pr.y * 4;
    const float l0 = u1[0] + u2[2] + sBp[0];
    const float l1 = u1[1] + u2[3] + sBp[1];
    const float m  = fmaxf(l0, l1);
    const float lse = m + logf(expf(l0 - m) + expf(l1 - m));
    float2* o2 = (float2*)(out + OFF_PAIR);
    o2[b * NP + tid] = make_float2(l0 - lse, l1 - lse);
}

// ---------------------------------------------------------------------------
extern "C" void kernel_launch(void* const* d_in, const int* in_sizes, int n_in,
                              void* d_out, int out_size)
{
    const float* emb  = (const float*)d_in[0];
    const int*   col  = (const int*)d_in[1];
    const int*   pidx = (const int*)d_in[2];
    const int wb = n_in - 14;
    const float* Wmsr  = (const float*)d_in[wb + 0];
    const float* bmsr  = (const float*)d_in[wb + 1];
    const float* Wagg  = (const float*)d_in[wb + 2];
    const float* bagg  = (const float*)d_in[wb + 3];
    const float* Wdim  = (const float*)d_in[wb + 4];
    const float* bdim  = (const float*)d_in[wb + 5];
    const float* Wmsrs = (const float*)d_in[wb + 6];
    const float* bmsrs = (const float*)d_in[wb + 7];
    const float* Wkey  = (const float*)d_in[wb + 8];
    const float* bkey  = (const float*)d_in[wb + 9];
    const float* Wpair = (const float*)d_in[wb + 10];
    const float* bpair = (const float*)d_in[wb + 11];
    const float* Wtype = (const float*)d_in[wb + 12];
    const float* btype = (const float*)d_in[wb + 13];
    float* out = (float*)d_out;

    k1_fused<<<dim3(NF / FG, NB), 192>>>(emb, col,
                                         Wmsr, bmsr, Wagg, bagg, Wdim, bdim,
                                         Wmsrs, bmsrs, Wkey, bkey,
                                         Wpair, Wtype, btype, out);

    k3_pair<<<NB, 256>>>(pidx, bpair, out);
}